// round 17
// baseline (speedup 1.0000x reference)
#include <cuda_runtime.h>
#include <cstdint>
#include <cstddef>

#define NCH    64
#define OCH    64
#define CONVCH 4096
#define HH     56
#define WW     56
#define PLANE  (HH*WW)     // 3136
#define NPIX   14
#define TROW   58          // full plane + 2 halo rows
#define TCOL   68          // 2-way-conflict-free-ish stride, rows 16B aligned
#define NJOB   (HH*14)     // 784 float4 fill jobs

typedef unsigned long long ull;

// One batch of deduplicated conv planes: conv[c][px], c in [0,4096)
__device__ float g_conv[(size_t)CONVCH * PLANE];   // 51.4 MB (L2-resident)

__device__ __forceinline__ ull pk2(float lo, float hi) {
    ull r; asm("mov.b64 %0, {%1, %2};" : "=l"(r) : "f"(lo), "f"(hi)); return r;
}
__device__ __forceinline__ float2 up2(ull p) {
    float2 r; asm("mov.b64 {%0, %1}, %2;" : "=f"(r.x), "=f"(r.y) : "l"(p)); return r;
}
__device__ __forceinline__ ull f2fma(ull a, ull b, ull c) {
    ull d; asm("fma.rn.f32x2 %0, %1, %2, %3;" : "=l"(d) : "l"(a), "l"(b), "l"(c)); return d;
}

// ---------------- conv: one block per conv channel, one batch per launch ----
__global__ __launch_bounds__(128)
void conv_kernel(const float* __restrict__ x,
                 const float* __restrict__ Wt,      // [4096,9]
                 const float* __restrict__ bias,    // [4096]
                 int b)
{
    __shared__ float tile[TROW][TCOL];   // 15.8 KB
    const int tid = threadIdx.x;
    const int c   = blockIdx.x;

    for (int j = tid; j < TROW*TCOL; j += 128) ((float*)tile)[j] = 0.f;
    __syncthreads();

    const float* xp = x + (size_t)(b*NCH + (c >> 6)) * PLANE;
    #pragma unroll
    for (int m = 0; m < 7; m++) {
        int j = tid + m*128;
        if (j < NJOB) {
            int rr = j / 14, cc = (j - rr*14) * 4;
            *(float4*)&tile[rr + 1][cc + 4] = *(const float4*)(xp + rr*WW + cc);
        }
    }
    __syncthreads();

    if (tid < 112) {
        const int tr = tid >> 2;        // row pair 0..27
        const int tx = tid & 3;
        const int ubase = 14*tx + 2;

        ull w[9];
        #pragma unroll
        for (int l = 0; l < 9; l++) { float v = __ldg(Wt + c*9 + l); w[l] = pk2(v, v); }
        float bv = __ldg(bias + c);
        const ull BP = pk2(bv, bv);

        ull SA[7], SB[7];
        #pragma unroll
        for (int j = 0; j < 7; j++) { SA[j] = BP; SB[j] = BP; }

        #pragma unroll
        for (int ky = 0; ky < 4; ky++) {
            const ull* rp = (const ull*)&tile[2*tr + ky][ubase];
            ull UP[9];
            #pragma unroll
            for (int m = 0; m < 9; m++) UP[m] = rp[m];
            ull E[8];
            #pragma unroll
            for (int j = 0; j < 8; j++) {
                float2 a = up2(UP[j]), cc = up2(UP[j+1]);
                E[j] = pk2(a.y, cc.x);
            }
            if (ky < 3) {
                #pragma unroll
                for (int j = 0; j < 7; j++)
                    SA[j] = f2fma(w[3*ky], E[j], f2fma(w[3*ky+1], UP[j+1], f2fma(w[3*ky+2], E[j+1], SA[j])));
            }
            if (ky > 0) {
                const int kb = ky - 1;
                #pragma unroll
                for (int j = 0; j < 7; j++)
                    SB[j] = f2fma(w[3*kb], E[j], f2fma(w[3*kb+1], UP[j+1], f2fma(w[3*kb+2], E[j+1], SB[j])));
            }
        }

        float* op = g_conv + (size_t)c*PLANE + (2*tr)*WW + tx*NPIX;
        #pragma unroll
        for (int j = 0; j < 7; j++) {
            *(float2*)(op + 2*j)      = up2(SA[j]);
            *(float2*)(op + WW + 2*j) = up2(SB[j]);
        }
    }
}

// ---------------- gather: max-over-g, mean-over-a, straight from L2 ---------
__global__ __launch_bounds__(196)
void gather_kernel(const void* __restrict__ index_raw,
                   float* __restrict__ out, int b)
{
    __shared__ int choff[128];
    const int tid = threadIdx.x;
    const int o   = blockIdx.x >> 2;
    const int q   = blockIdx.x & 3;

    // index dtype detection (int32 if JAX x64 off, else int64)
    const int* idx32 = (const int*)index_raw;
    const bool is64 = ((idx32[1] | idx32[3] | idx32[5] | idx32[7]) == 0);
    if (tid < 128) {
        int j = o*128 + tid;
        int v = is64 ? (int)((const long long*)index_raw)[j] : idx32[j];
        choff[tid] = (v & (CONVCH - 1)) * PLANE;
    }
    __syncthreads();

    const int px = (q*196 + tid) * 4;          // 784 float4 per plane, 196/block
    const float* cb = g_conv + px;

    float4 acc = make_float4(0.f, 0.f, 0.f, 0.f);
    #pragma unroll 2
    for (int a = 0; a < 16; a++) {
        const int* ch = &choff[a*8];
        float4 mx = *(const float4*)(cb + ch[0]);
        #pragma unroll
        for (int g = 1; g < 8; g++) {
            float4 v = *(const float4*)(cb + ch[g]);
            mx.x = fmaxf(mx.x, v.x);
            mx.y = fmaxf(mx.y, v.y);
            mx.z = fmaxf(mx.z, v.z);
            mx.w = fmaxf(mx.w, v.w);
        }
        acc.x += mx.x; acc.y += mx.y; acc.z += mx.z; acc.w += mx.w;
    }
    acc.x *= 0.0625f; acc.y *= 0.0625f; acc.z *= 0.0625f; acc.w *= 0.0625f;

    *(float4*)(out + (size_t)(b*OCH + o)*PLANE + px) = acc;
}

extern "C" void kernel_launch(void* const* d_in, const int* in_sizes, int n_in,
                              void* d_out, int out_size) {
    const float* x    = (const float*)d_in[0];
    const float* Wt   = (const float*)d_in[1];
    const float* bias = (const float*)d_in[2];
    const void*  idx  = (const void*)d_in[3];
    float* out = (float*)d_out;
    for (int b = 0; b < 8; b++) {
        conv_kernel<<<CONVCH, 128>>>(x, Wt, bias, b);
        gather_kernel<<<OCH * 4, 196>>>(idx, out, b);
    }
}